// round 13
// baseline (speedup 1.0000x reference)
#include <cuda_runtime.h>
#include <cuda_fp16.h>
#include <cstdint>
#include <cstring>

#define NN 50000
#define EE 250000
#define HH 4
#define CC 64
#define DNODE 256
#define EDD 194
#define KS 256          // quantized K stride
#define NOUT 256
#define KEDGE 224
#define QMAX 16256.0f   // 127*128

// ---------------- scratch (device globals; no runtime allocation) ----------------
__device__ float  g_q   [(size_t)NN * DNODE];
__device__ float  g_k   [(size_t)NN * DNODE];
__device__ float  g_v   [(size_t)NN * DNODE];
__device__ float  g_skip[(size_t)NN * DNODE];
__device__ __half g_eh  [(size_t)EE * DNODE];   // edge embeddings, fp16, original order

// edge sort-by-dst
__device__ int g_cnt [NN];
__device__ int g_off [NN + 1];
__device__ int g_pos [NN];
__device__ int g_order[EE];
__device__ int g_srcs [EE];

// int8 two-limb operands
__device__ int8_t g_ah[(size_t)NN * KS];
__device__ int8_t g_al[(size_t)NN * KS];
__device__ int8_t g_eqh[(size_t)EE * KS];
__device__ int8_t g_eql[(size_t)EE * KS];
// weights: per layer rows [Wq|Wk|Wv|Ws](1024) + We(256) = 1280 rows; 2 layers = 2560
__device__ int8_t g_wh[(size_t)2560 * KS];
__device__ int8_t g_wl[(size_t)2560 * KS];
__device__ float  g_sa[NN];
__device__ float  g_se[EE];
__device__ float  g_sw[2560];
__device__ float  g_bias[2][4 * NOUT];

// ==================== int8 two-limb IMMA GEMM ====================
#define BM 128
#define BN 64
#define BK 32
#define NTHR 512
#define NSTAGE 3
#define LDS8 48
#define ATSZ (128 * LDS8)          // 6144
#define WTSZ (64 * LDS8)           // 3072
#define STG  (2 * ATSZ + 2 * WTSZ) // 18432
#define GEMM_SMEM (NSTAGE * STG)   // 55296

__device__ __forceinline__ uint32_t smem_u32(const void* p) {
    uint32_t a;
    asm("{ .reg .u64 t; cvta.to.shared.u64 t, %1; cvt.u32.u64 %0, t; }" : "=r"(a) : "l"(p));
    return a;
}
__device__ __forceinline__ void cpa16(uint32_t dst, const void* src, int szbytes) {
    asm volatile("cp.async.ca.shared.global [%0], [%1], 16, %2;"
                 :: "r"(dst), "l"(src), "r"(szbytes));
}
#define CP_COMMIT() asm volatile("cp.async.commit_group;" ::: "memory")
#define CP_WAIT(n)  asm volatile("cp.async.wait_group %0;" :: "n"(n) : "memory")

__device__ __forceinline__ void ldsm4(uint32_t* r, uint32_t a) {
    asm volatile("ldmatrix.sync.aligned.m8n8.x4.shared.b16 {%0,%1,%2,%3}, [%4];"
                 : "=r"(r[0]), "=r"(r[1]), "=r"(r[2]), "=r"(r[3]) : "r"(a));
}
__device__ __forceinline__ void mma_s8(int* c, const uint32_t* a, const uint32_t* b) {
    asm volatile(
        "mma.sync.aligned.m16n8k32.row.col.s32.s8.s8.s32 "
        "{%0,%1,%2,%3}, {%4,%5,%6,%7}, {%8,%9}, {%0,%1,%2,%3};"
        : "+r"(c[0]), "+r"(c[1]), "+r"(c[2]), "+r"(c[3])
        : "r"(a[0]), "r"(a[1]), "r"(a[2]), "r"(a[3]), "r"(b[0]), "r"(b[1]));
}

// If EH != nullptr: fp16 epilogue (edge GEMM). Else fp32 + bias into C0..C3
// (blockIdx.y>>2 selects buffer, (blockIdx.y&3)*64 is col offset).
__global__ __launch_bounds__(NTHR) void gemm_q(
    const int8_t* __restrict__ Ah, const int8_t* __restrict__ Al,
    const int8_t* __restrict__ Wh, const int8_t* __restrict__ Wl,
    const float* __restrict__ sa, const float* __restrict__ sw,
    const float* __restrict__ bias,
    float* __restrict__ C0, float* __restrict__ C1,
    float* __restrict__ C2, float* __restrict__ C3,
    __half* __restrict__ EH, int M, int K)
{
    extern __shared__ int8_t smem[];

    const int tid  = threadIdx.x;
    const int wid  = tid >> 5;
    const int lane = tid & 31;
    const int m0   = blockIdx.x * BM;
    const int nglob0 = blockIdx.y * BN;

    const int wm = (wid & 3) * 32;
    const int wn = (wid >> 2) * 16;
    const int gr  = lane >> 2;
    const int tig = lane & 3;

    // loader: row = tid>>2 (0..127), arr = tid&3 in {Ah, Al, Wh, Wl}
    const int row = tid >> 2;
    const int arr = tid & 3;
    const int gmA = m0 + row;
    const int aok = (gmA < M) ? 16 : 0;
    const size_t arowq = (size_t)(aok ? gmA : 0) * KS;
    const size_t wrowq = (size_t)(nglob0 + (row & 63)) * KS;

    const int nk = K / BK;

    int hh[2][2][4], xx[2][2][4];
#pragma unroll
    for (int i = 0; i < 2; i++)
#pragma unroll
        for (int j = 0; j < 2; j++)
#pragma unroll
            for (int r = 0; r < 4; r++) { hh[i][j][r] = 0; xx[i][j][r] = 0; }

    uint32_t sbase = smem_u32(smem);

    auto load_stage = [&](int st, int kc) {
        uint32_t b = sbase + (uint32_t)(st * STG);
        if (arr < 2) {
            uint32_t d = b + (uint32_t)(arr * ATSZ + row * LDS8);
            const int8_t* s = (arr ? Al : Ah) + arowq + kc;
            cpa16(d, s, aok);
            cpa16(d + 16, s + 16, aok);
        } else if (row < 64) {
            uint32_t d = b + (uint32_t)(2 * ATSZ + (arr - 2) * WTSZ + row * LDS8);
            const int8_t* s = ((arr == 2) ? Wh : Wl) + wrowq + kc;
            cpa16(d, s, 16);
            cpa16(d + 16, s + 16, 16);
        }
        CP_COMMIT();
    };

    // ldmatrix byte offsets (stride 48B, conflict-free)
    const uint32_t aOff = (uint32_t)((wm + (lane & 15)) * LDS8 + (lane >> 4) * 16);
    const uint32_t bOff = (uint32_t)((wn + (lane & 7) + ((lane >> 4) << 3)) * LDS8
                                     + ((lane >> 3) & 1) * 16);

    load_stage(0, 0);
    if (nk > 1) load_stage(1, BK);

    for (int ki = 0; ki < nk; ki++) {
        if (ki + 2 < nk) {
            load_stage((ki + 2) % NSTAGE, (ki + 2) * BK);
            CP_WAIT(2);
        } else if (ki + 1 < nk) {
            CP_WAIT(1);
        } else {
            CP_WAIT(0);
        }
        __syncthreads();

        uint32_t stb = sbase + (uint32_t)((ki % NSTAGE) * STG);
        uint32_t aH = stb, aL = stb + ATSZ;
        uint32_t bH = stb + 2 * ATSZ, bL = stb + 2 * ATSZ + WTSZ;

        uint32_t af[2][4], lf[2][4], bh[4], bl[4];
#pragma unroll
        for (int mt = 0; mt < 2; mt++) {
            uint32_t o = aOff + (uint32_t)(mt * 16 * LDS8);
            ldsm4(af[mt], aH + o);
            ldsm4(lf[mt], aL + o);
        }
        ldsm4(bh, bH + bOff);
        ldsm4(bl, bL + bOff);

#pragma unroll
        for (int mt = 0; mt < 2; mt++)
#pragma unroll
            for (int nt = 0; nt < 2; nt++) {
                mma_s8(hh[mt][nt], af[mt], bh + nt * 2);
                mma_s8(xx[mt][nt], af[mt], bl + nt * 2);
                mma_s8(xx[mt][nt], lf[mt], bh + nt * 2);
            }
        __syncthreads();
    }

    // ---- epilogue: C = (16384*HH + 128*X) * sa[m] * sw[n] (+bias) ----
    if (EH == nullptr) {
        const int ob = blockIdx.y >> 2;
        float* C = (ob == 0) ? C0 : (ob == 1) ? C1 : (ob == 2) ? C2 : C3;
        const int n0l = (blockIdx.y & 3) * BN;
#pragma unroll
        for (int nt = 0; nt < 2; nt++) {
            int lc = wn + nt * 8 + tig * 2;
            int ng = nglob0 + lc;
            float2 swv = *(const float2*)(sw + ng);
            float2 b2  = *(const float2*)(bias + ng);
            int gc = n0l + lc;
#pragma unroll
            for (int mt = 0; mt < 2; mt++) {
                int gm = m0 + wm + mt * 16 + gr;
                if (gm < M) {
                    float s0 = sa[gm];
                    float2 o;
                    o.x = (16384.f * (float)hh[mt][nt][0] + 128.f * (float)xx[mt][nt][0]) * (s0 * swv.x) + b2.x;
                    o.y = (16384.f * (float)hh[mt][nt][1] + 128.f * (float)xx[mt][nt][1]) * (s0 * swv.y) + b2.y;
                    *(float2*)(C + (size_t)gm * NOUT + gc) = o;
                }
                if (gm + 8 < M) {
                    float s1 = sa[gm + 8];
                    float2 o;
                    o.x = (16384.f * (float)hh[mt][nt][2] + 128.f * (float)xx[mt][nt][2]) * (s1 * swv.x) + b2.x;
                    o.y = (16384.f * (float)hh[mt][nt][3] + 128.f * (float)xx[mt][nt][3]) * (s1 * swv.y) + b2.y;
                    *(float2*)(C + (size_t)(gm + 8) * NOUT + gc) = o;
                }
            }
        }
    } else {
#pragma unroll
        for (int nt = 0; nt < 2; nt++) {
            int lc = wn + nt * 8 + tig * 2;
            int ng = nglob0 + lc;
            float2 swv = *(const float2*)(sw + ng);
#pragma unroll
            for (int mt = 0; mt < 2; mt++) {
                int gm = m0 + wm + mt * 16 + gr;
                if (gm < M) {
                    float s0 = sa[gm];
                    float ox = (16384.f * (float)hh[mt][nt][0] + 128.f * (float)xx[mt][nt][0]) * (s0 * swv.x);
                    float oy = (16384.f * (float)hh[mt][nt][1] + 128.f * (float)xx[mt][nt][1]) * (s0 * swv.y);
                    *(__half2*)(EH + (size_t)gm * NOUT + ng) = __floats2half2_rn(ox, oy);
                }
                if (gm + 8 < M) {
                    float s1 = sa[gm + 8];
                    float ox = (16384.f * (float)hh[mt][nt][2] + 128.f * (float)xx[mt][nt][2]) * (s1 * swv.x);
                    float oy = (16384.f * (float)hh[mt][nt][3] + 128.f * (float)xx[mt][nt][3]) * (s1 * swv.y);
                    *(__half2*)(EH + (size_t)(gm + 8) * NOUT + ng) = __floats2half2_rn(ox, oy);
                }
            }
        }
    }
}

// ==================== quantization kernels ====================
__device__ __forceinline__ void quant8(const float* vals, float inv,
                                       int8_t* hb, int8_t* lb)
{
#pragma unroll
    for (int j = 0; j < 8; j++) {
        int q = __float2int_rn(vals[j] * inv);
        int h = (q + ((q >= 0) ? 64 : -64)) / 128;
        int l = q - (h << 7);
        hb[j] = (int8_t)h;
        lb[j] = (int8_t)l;
    }
}

// one warp per row of X [M x Kin] -> hq/lq [M x KS], scale s[M]
__global__ void quant_feat(const float* __restrict__ X, int M, int Kin,
                           int8_t* __restrict__ hq, int8_t* __restrict__ lq,
                           float* __restrict__ s)
{
    int w = (blockIdx.x * blockDim.x + threadIdx.x) >> 5;
    if (w >= M) return;
    int lane = threadIdx.x & 31;
    float vals[8];
    float m = 0.f;
#pragma unroll
    for (int j = 0; j < 8; j++) {
        int k = lane * 8 + j;
        float v = (k < Kin) ? X[(size_t)w * Kin + k] : 0.f;
        vals[j] = v;
        m = fmaxf(m, fabsf(v));
    }
#pragma unroll
    for (int d = 16; d; d >>= 1) m = fmaxf(m, __shfl_xor_sync(0xffffffffu, m, d));
    float inv = (m > 0.f) ? (QMAX / m) : 0.f;
    int8_t hb[8], lb[8];
    quant8(vals, inv, hb, lb);
    uint64_t hu, lu;
    memcpy(&hu, hb, 8); memcpy(&lu, lb, 8);
    *(uint64_t*)(hq + (size_t)w * KS + lane * 8) = hu;
    *(uint64_t*)(lq + (size_t)w * KS + lane * 8) = lu;
    if (lane == 0) s[w] = m / QMAX;
}

// one warp per output n-row of W [Kin x 256] (transposed store)
__global__ void quant_weight(const float* __restrict__ W, int Kin,
                             int8_t* __restrict__ hq, int8_t* __restrict__ lq,
                             float* __restrict__ s)
{
    int w = (blockIdx.x * blockDim.x + threadIdx.x) >> 5;
    if (w >= NOUT) return;
    int lane = threadIdx.x & 31;
    float vals[8];
    float m = 0.f;
#pragma unroll
    for (int j = 0; j < 8; j++) {
        int k = lane * 8 + j;
        float v = (k < Kin) ? W[(size_t)k * NOUT + w] : 0.f;
        vals[j] = v;
        m = fmaxf(m, fabsf(v));
    }
#pragma unroll
    for (int d = 16; d; d >>= 1) m = fmaxf(m, __shfl_xor_sync(0xffffffffu, m, d));
    float inv = (m > 0.f) ? (QMAX / m) : 0.f;
    int8_t hb[8], lb[8];
    quant8(vals, inv, hb, lb);
    uint64_t hu, lu;
    memcpy(&hu, hb, 8); memcpy(&lu, lb, 8);
    *(uint64_t*)(hq + (size_t)w * KS + lane * 8) = hu;
    *(uint64_t*)(lq + (size_t)w * KS + lane * 8) = lu;
    if (lane == 0) s[w] = m / QMAX;
}

__global__ void pack_bias(const float* __restrict__ bq, const float* __restrict__ bk,
                          const float* __restrict__ bv, const float* __restrict__ bs,
                          float* __restrict__ out)
{
    int i = blockIdx.x * blockDim.x + threadIdx.x;
    if (i >= 4 * NOUT) return;
    const float* src = (i < 256) ? bq : (i < 512) ? bk : (i < 768) ? bv : bs;
    out[i] = src[i & 255];
}

// ==================== edge sort-by-dst ====================
__global__ void zero_cnt(int* __restrict__ cnt) {
    int i = blockIdx.x * blockDim.x + threadIdx.x;
    if (i < NN) cnt[i] = 0;
}
__global__ void hist_dst(const int* __restrict__ dst, int* __restrict__ cnt) {
    int i = blockIdx.x * blockDim.x + threadIdx.x;
    if (i < EE) atomicAdd(&cnt[dst[i]], 1);
}
__global__ __launch_bounds__(1024) void scan_cnt(const int* __restrict__ cnt,
                                                 int* __restrict__ off, int* __restrict__ pos)
{
    __shared__ int ssum[1024];
    const int tid = threadIdx.x;
    const int PER = (NN + 1023) / 1024;
    const int base = tid * PER;
    int s = 0;
    for (int j = 0; j < PER; j++) {
        int i = base + j;
        if (i < NN) s += cnt[i];
    }
    ssum[tid] = s;
    __syncthreads();
    for (int d = 1; d < 1024; d <<= 1) {
        int t = (tid >= d) ? ssum[tid - d] : 0;
        __syncthreads();
        ssum[tid] += t;
        __syncthreads();
    }
    int run = (tid > 0) ? ssum[tid - 1] : 0;
    for (int j = 0; j < PER; j++) {
        int i = base + j;
        if (i < NN) {
            off[i] = run;
            pos[i] = run;
            run += cnt[i];
        }
    }
    if (tid == 1023) off[NN] = run;
}
__global__ void scatter_edges(const int* __restrict__ dst, const int* __restrict__ src,
                              int* __restrict__ pos, int* __restrict__ order,
                              int* __restrict__ srcs)
{
    int i = blockIdx.x * blockDim.x + threadIdx.x;
    if (i >= EE) return;
    int p = atomicAdd(&pos[dst[i]], 1);
    order[p] = i;
    srcs[p] = src[i];
}

// ==================== fused per-dst attention ====================
// mode 1: relu + int8 two-limb quantize into (hq, lq, saout)  — layer-2 GEMM input
// mode 0: write float out
__global__ __launch_bounds__(256) void edge_dst(
    const float* __restrict__ q, const float* __restrict__ k,
    const __half* __restrict__ eemb, const float* __restrict__ v,
    const int* __restrict__ srcs, const int* __restrict__ order,
    const int* __restrict__ off, const float* __restrict__ skip,
    float* __restrict__ outf,
    int8_t* __restrict__ hq, int8_t* __restrict__ lq, float* __restrict__ saout,
    int mode)
{
    int w = (blockIdx.x * blockDim.x + threadIdx.x) >> 5;
    if (w >= NN) return;
    const int lane = threadIdx.x & 31;
    const int h = lane >> 3;
    const int part = lane & 7;
    const int co = h * CC + part * 8;

    const int start = off[w], end = off[w + 1];

    const float4* qp = (const float4*)(q + (size_t)w * DNODE + co);
    float4 q0 = qp[0], q1 = qp[1];

    float acc[8] = {0.f, 0.f, 0.f, 0.f, 0.f, 0.f, 0.f, 0.f};
    float den = 0.f;

    for (int i = start; i < end; i++) {
        int s = srcs[i];
        int e = order[i];
        const float4* kp = (const float4*)(k + (size_t)s * DNODE + co);
        float4 k0 = kp[0], k1 = kp[1];

        uint4 eu = *(const uint4*)(eemb + (size_t)e * DNODE + co);
        const __half2* hp = (const __half2*)&eu;
        float2 ea = __half22float2(hp[0]);
        float2 eb = __half22float2(hp[1]);
        float2 ec = __half22float2(hp[2]);
        float2 ed = __half22float2(hp[3]);
        float4 e0 = make_float4(ea.x, ea.y, eb.x, eb.y);
        float4 e1 = make_float4(ec.x, ec.y, ed.x, ed.y);

        float dot = q0.x * (k0.x + e0.x) + q0.y * (k0.y + e0.y)
                  + q0.z * (k0.z + e0.z) + q0.w * (k0.w + e0.w)
                  + q1.x * (k1.x + e1.x) + q1.y * (k1.y + e1.y)
                  + q1.z * (k1.z + e1.z) + q1.w * (k1.w + e1.w);
        dot += __shfl_xor_sync(0xffffffffu, dot, 1);
        dot += __shfl_xor_sync(0xffffffffu, dot, 2);
        dot += __shfl_xor_sync(0xffffffffu, dot, 4);

        float ex = __expf(dot * 0.125f);
        den += ex;

        const float4* vp = (const float4*)(v + (size_t)s * DNODE + co);
        float4 v0 = vp[0], v1 = vp[1];
        acc[0] += ex * (v0.x + e0.x); acc[1] += ex * (v0.y + e0.y);
        acc[2] += ex * (v0.z + e0.z); acc[3] += ex * (v0.w + e0.w);
        acc[4] += ex * (v1.x + e1.x); acc[5] += ex * (v1.y + e1.y);
        acc[6] += ex * (v1.z + e1.z); acc[7] += ex * (v1.w + e1.w);
    }

    float inv = 1.0f / (den + 1e-16f);
    const float4* sp = (const float4*)(skip + (size_t)w * DNODE + co);
    float4 s0 = sp[0], s1 = sp[1];
    float r[8];
    r[0] = acc[0] * inv + s0.x; r[1] = acc[1] * inv + s0.y;
    r[2] = acc[2] * inv + s0.z; r[3] = acc[3] * inv + s0.w;
    r[4] = acc[4] * inv + s1.x; r[5] = acc[5] * inv + s1.y;
    r[6] = acc[6] * inv + s1.z; r[7] = acc[7] * inv + s1.w;

    if (mode == 1) {
        // relu + warp-wide row max + int8 two-limb quantize
        float m = 0.f;
#pragma unroll
        for (int j = 0; j < 8; j++) {
            r[j] = fmaxf(r[j], 0.f);
            m = fmaxf(m, r[j]);
        }
#pragma unroll
        for (int d = 16; d; d >>= 1) m = fmaxf(m, __shfl_xor_sync(0xffffffffu, m, d));
        float qinv = (m > 0.f) ? (QMAX / m) : 0.f;
        int8_t hb[8], lb[8];
        quant8(r, qinv, hb, lb);
        uint64_t hu, lu;
        memcpy(&hu, hb, 8); memcpy(&lu, lb, 8);
        *(uint64_t*)(hq + (size_t)w * KS + co) = hu;
        *(uint64_t*)(lq + (size_t)w * KS + co) = lu;
        if (lane == 0) saout[w] = m / QMAX;
    } else {
        float4* op = (float4*)(outf + (size_t)w * DNODE + co);
        op[0] = make_float4(r[0], r[1], r[2], r[3]);
        op[1] = make_float4(r[4], r[5], r[6], r[7]);
    }
}

// ==================== host side ====================
extern "C" void kernel_launch(void* const* d_in, const int* in_sizes, int n_in,
                              void* d_out, int out_size)
{
    const float* x   = (const float*)d_in[0];
    const int*   ei  = (const int*)  d_in[1];
    const float* ea  = (const float*)d_in[2];
    // per layer, weight buffer row order: Wq, Wk, Wv, Ws, We
    const float* W1[5] = { (const float*)d_in[3],  (const float*)d_in[5],
                           (const float*)d_in[7],  (const float*)d_in[10],
                           (const float*)d_in[9] };
    const float* W2[5] = { (const float*)d_in[12], (const float*)d_in[14],
                           (const float*)d_in[16], (const float*)d_in[19],
                           (const float*)d_in[18] };
    const int Kin[5] = { DNODE, DNODE, DNODE, DNODE, EDD };

    const int* src = ei;
    const int* dst = ei + EE;
    float* out = (float*)d_out;

    float *q, *k, *v, *skip, *bias, *sa, *se, *sw;
    __half* eh;
    int *cnt, *off, *pos, *order, *srcs;
    int8_t *ah, *al, *eqh, *eql, *wh, *wl;
    cudaGetSymbolAddress((void**)&q,     g_q);
    cudaGetSymbolAddress((void**)&k,     g_k);
    cudaGetSymbolAddress((void**)&v,     g_v);
    cudaGetSymbolAddress((void**)&skip,  g_skip);
    cudaGetSymbolAddress((void**)&eh,    g_eh);
    cudaGetSymbolAddress((void**)&cnt,   g_cnt);
    cudaGetSymbolAddress((void**)&off,   g_off);
    cudaGetSymbolAddress((void**)&pos,   g_pos);
    cudaGetSymbolAddress((void**)&order, g_order);
    cudaGetSymbolAddress((void**)&srcs,  g_srcs);
    cudaGetSymbolAddress((void**)&ah,    g_ah);
    cudaGetSymbolAddress((void**)&al,    g_al);
    cudaGetSymbolAddress((void**)&eqh,   g_eqh);
    cudaGetSymbolAddress((void**)&eql,   g_eql);
    cudaGetSymbolAddress((void**)&wh,    g_wh);
    cudaGetSymbolAddress((void**)&wl,    g_wl);
    cudaGetSymbolAddress((void**)&sa,    g_sa);
    cudaGetSymbolAddress((void**)&se,    g_se);
    cudaGetSymbolAddress((void**)&sw,    g_sw);
    cudaGetSymbolAddress((void**)&bias,  g_bias);

    cudaFuncSetAttribute(gemm_q, cudaFuncAttributeMaxDynamicSharedMemorySize, GEMM_SMEM);

    // ---- edge sort by dst (once; shared by both layers) ----
    zero_cnt<<<(NN + 255) / 256, 256>>>(cnt);
    hist_dst<<<(EE + 255) / 256, 256>>>(dst, cnt);
    scan_cnt<<<1, 1024>>>(cnt, off, pos);
    scatter_edges<<<(EE + 255) / 256, 256>>>(dst, src, pos, order, srcs);

    // ---- quantize weights (rows: layer*1280 + i*256) + biases ----
    for (int i = 0; i < 5; i++) {
        size_t b1 = (size_t)(0    + i * 256);
        size_t b2 = (size_t)(1280 + i * 256);
        quant_weight<<<32, 256>>>(W1[i], Kin[i], wh + b1 * KS, wl + b1 * KS, sw + b1);
        quant_weight<<<32, 256>>>(W2[i], Kin[i], wh + b2 * KS, wl + b2 * KS, sw + b2);
    }
    pack_bias<<<4, 256>>>((const float*)d_in[4],  (const float*)d_in[6],
                          (const float*)d_in[8],  (const float*)d_in[11], bias);
    pack_bias<<<4, 256>>>((const float*)d_in[13], (const float*)d_in[15],
                          (const float*)d_in[17], (const float*)d_in[20], bias + 4 * NOUT);

    // ---- quantize features ----
    quant_feat<<<(NN * 32 + 255) / 256, 256>>>(x,  NN, DNODE, ah,  al,  sa);
    quant_feat<<<(EE * 32 + 255) / 256, 256>>>(ea, EE, EDD,   eqh, eql, se);

    dim3 gn((NN + BM - 1) / BM, 16);
    dim3 ge((EE + BM - 1) / BM, 4);

    // ---- layer 1 ----
    gemm_q<<<gn, NTHR, GEMM_SMEM>>>(ah, al, wh, wl, sa, sw, bias,
                                    q, k, v, skip, nullptr, NN, KS);
    gemm_q<<<ge, NTHR, GEMM_SMEM>>>(eqh, eql, wh + (size_t)1024 * KS, wl + (size_t)1024 * KS,
                                    se, sw + 1024, nullptr,
                                    nullptr, nullptr, nullptr, nullptr, eh, EE, KEDGE);
    edge_dst<<<(NN * 32 + 255) / 256, 256>>>(q, k, eh, v, srcs, order, off, skip,
                                             nullptr, ah, al, sa, 1);

    // ---- layer 2 ----
    gemm_q<<<gn, NTHR, GEMM_SMEM>>>(ah, al, wh + (size_t)1280 * KS, wl + (size_t)1280 * KS,
                                    sa, sw + 1280, bias + 4 * NOUT,
                                    q, k, v, skip, nullptr, NN, KS);
    gemm_q<<<ge, NTHR, GEMM_SMEM>>>(eqh, eql, wh + (size_t)2304 * KS, wl + (size_t)2304 * KS,
                                    se, sw + 2304, nullptr,
                                    nullptr, nullptr, nullptr, nullptr, eh, EE, KEDGE);
    edge_dst<<<(NN * 32 + 255) / 256, 256>>>(q, k, eh, v, srcs, order, off, skip,
                                             out, nullptr, nullptr, nullptr, 0);
}

// round 14
// speedup vs baseline: 1.7796x; 1.7796x over previous
#include <cuda_runtime.h>
#include <cuda_bf16.h>
#include <cuda_fp16.h>
#include <cstdint>

#define NN 50000
#define EE 250000
#define HH 4
#define CC 64
#define DNODE 256
#define EDD 194
#define KPAD 256
#define NOUT 256
#define KEDGE 224

// ---------------- scratch (device globals; no runtime allocation) ----------------
__device__ float  g_q   [(size_t)NN * DNODE];
__device__ float  g_k   [(size_t)NN * DNODE];
__device__ float  g_v   [(size_t)NN * DNODE];
__device__ float  g_skip[(size_t)NN * DNODE];
__device__ __half g_eh  [(size_t)EE * DNODE];   // edge embeddings, fp16, original order

// edge sort-by-dst (once per call; edge_index identical for both layers)
__device__ int g_cnt [NN];
__device__ int g_off [NN + 1];
__device__ int g_pos [NN];
__device__ int g_order[EE];
__device__ int g_srcs [EE];

// split-bf16 operand buffers
__device__ __nv_bfloat16 g_ahi[(size_t)NN * KPAD];
__device__ __nv_bfloat16 g_alo[(size_t)NN * KPAD];
__device__ __nv_bfloat16 g_ehi[(size_t)EE * KPAD];
__device__ __nv_bfloat16 g_elo[(size_t)EE * KPAD];
// per layer: [Wq|Wk|Wv|Ws] (4*256 rows) then We (256 rows); 2 layers
__device__ __nv_bfloat16 g_whi[10][(size_t)NOUT * KPAD];
__device__ __nv_bfloat16 g_wlo[10][(size_t)NOUT * KPAD];
__device__ float g_bias[2][4 * NOUT];

// ==================== split-bf16 HMMA GEMM (R12 core, single-barrier pipeline) ====================
#define BM 128
#define BN 128
#define BK 32
#define NTHR 512
#define NSTAGE 3
#define LDS_A 40
#define TSZ (BM * LDS_A)
#define STAGE_ELEMS (4 * TSZ)
#define GEMM_SMEM (NSTAGE * STAGE_ELEMS * 2)

__device__ __forceinline__ uint32_t smem_u32(const void* p) {
    uint32_t a;
    asm("{ .reg .u64 t; cvta.to.shared.u64 t, %1; cvt.u32.u64 %0, t; }" : "=r"(a) : "l"(p));
    return a;
}
__device__ __forceinline__ void cpa16(uint32_t dst, const void* src, int szbytes) {
    asm volatile("cp.async.ca.shared.global [%0], [%1], 16, %2;"
                 :: "r"(dst), "l"(src), "r"(szbytes));
}
#define CP_COMMIT() asm volatile("cp.async.commit_group;" ::: "memory")
#define CP_WAIT(n)  asm volatile("cp.async.wait_group %0;" :: "n"(n) : "memory")

__device__ __forceinline__ void ldsm4(uint32_t* r, uint32_t a) {
    asm volatile("ldmatrix.sync.aligned.m8n8.x4.shared.b16 {%0,%1,%2,%3}, [%4];"
                 : "=r"(r[0]), "=r"(r[1]), "=r"(r[2]), "=r"(r[3]) : "r"(a));
}
__device__ __forceinline__ void mma_bf16(float* c, const uint32_t* a, const uint32_t* b) {
    asm volatile(
        "mma.sync.aligned.m16n8k16.row.col.f32.bf16.bf16.f32 "
        "{%0,%1,%2,%3}, {%4,%5,%6,%7}, {%8,%9}, {%0,%1,%2,%3};"
        : "+f"(c[0]), "+f"(c[1]), "+f"(c[2]), "+f"(c[3])
        : "r"(a[0]), "r"(a[1]), "r"(a[2]), "r"(a[3]), "r"(b[0]), "r"(b[1]));
}

// If EH != nullptr: fp16 epilogue into EH (edge GEMM). Else fp32 into C0..C3 + bias.
__global__ __launch_bounds__(NTHR) void gemm_split(
    const __nv_bfloat16* __restrict__ Ahi, const __nv_bfloat16* __restrict__ Alo,
    const __nv_bfloat16* __restrict__ Bhi, const __nv_bfloat16* __restrict__ Blo,
    const float* __restrict__ bias,
    float* __restrict__ C0, float* __restrict__ C1,
    float* __restrict__ C2, float* __restrict__ C3,
    __half* __restrict__ EH,
    int M, int K)
{
    extern __shared__ __nv_bfloat16 smem[];

    const int tid  = threadIdx.x;
    const int wid  = tid >> 5;
    const int lane = tid & 31;
    const int m0   = blockIdx.x * BM;
    const int nglob0 = blockIdx.y * BN;

    const int wm = (wid & 3) * 32;
    const int wn = (wid >> 2) * 32;
    const int gr  = lane >> 2;
    const int tig = lane & 3;

    const int r0  = tid >> 2;
    const int cg0 = (tid & 3) * 8;
    const int gmA = m0 + r0;
    const int aok = (gmA < M) ? 16 : 0;
    const size_t arow = (size_t)(aok ? gmA : 0) * KPAD;
    const size_t brow = (size_t)(nglob0 + r0) * KPAD;

    const int nk = K / BK;

    float acc[2][4][4];
#pragma unroll
    for (int i = 0; i < 2; i++)
#pragma unroll
        for (int j = 0; j < 4; j++)
#pragma unroll
            for (int r = 0; r < 4; r++) acc[i][j][r] = 0.f;

    uint32_t sbase = smem_u32(smem);

    auto load_stage = [&](int st, int kc) {
        uint32_t b = sbase + (uint32_t)(st * STAGE_ELEMS) * 2;
        uint32_t d = b + (uint32_t)(r0 * LDS_A + cg0) * 2;
        cpa16(d,                    Ahi + arow + kc + cg0, aok);
        cpa16(d + (uint32_t)TSZ*2,  Alo + arow + kc + cg0, aok);
        cpa16(d + (uint32_t)TSZ*4,  Bhi + brow + kc + cg0, 16);
        cpa16(d + (uint32_t)TSZ*6,  Blo + brow + kc + cg0, 16);
        CP_COMMIT();
    };

    const int aRow = lane & 15;
    const int aCol = (lane >> 4) * 8;
    const uint32_t aOff = (uint32_t)((wm + aRow) * LDS_A + aCol) * 2;
    const int bRow = wn + (lane & 7) + ((lane >> 4) << 3);
    const int bCol = ((lane >> 3) & 1) * 8;
    const uint32_t bOff = (uint32_t)(bRow * LDS_A + bCol) * 2;

    load_stage(0, 0);
    if (nk > 1) load_stage(1, BK);

    // single-barrier multistage main loop:
    // at iter ki: wait stage ki ready -> barrier -> compute(ki) -> issue stage ki+2
    for (int ki = 0; ki < nk; ki++) {
        if (ki + 1 < nk) {
            CP_WAIT(1);
        } else {
            CP_WAIT(0);
        }
        __syncthreads();

        uint32_t stb = sbase + (uint32_t)((ki % NSTAGE) * STAGE_ELEMS) * 2;
        uint32_t aHiB = stb, aLoB = stb + TSZ * 2;
        uint32_t bHiB = stb + TSZ * 4, bLoB = stb + TSZ * 6;

#pragma unroll
        for (int ks = 0; ks < BK; ks += 16) {
            uint32_t ah[2][4], al[2][4];
#pragma unroll
            for (int mt = 0; mt < 2; mt++) {
                uint32_t o = aOff + (uint32_t)(mt * 16 * LDS_A + ks) * 2;
                ldsm4(ah[mt], aHiB + o);
                ldsm4(al[mt], aLoB + o);
            }
            uint32_t bhf[8], blf[8];
#pragma unroll
            for (int p = 0; p < 2; p++) {
                uint32_t o = bOff + (uint32_t)(p * 16 * LDS_A + ks) * 2;
                ldsm4(bhf + 4 * p, bHiB + o);
                ldsm4(blf + 4 * p, bLoB + o);
            }
#pragma unroll
            for (int mt = 0; mt < 2; mt++)
#pragma unroll
                for (int nt = 0; nt < 4; nt++) {
                    mma_bf16(acc[mt][nt], ah[mt], bhf + nt * 2);
                    mma_bf16(acc[mt][nt], ah[mt], blf + nt * 2);
                    mma_bf16(acc[mt][nt], al[mt], bhf + nt * 2);
                }
        }

        if (ki + 2 < nk) load_stage((ki + 2) % NSTAGE, (ki + 2) * BK);
    }

    // ---- epilogue ----
    if (EH == nullptr) {
        const int ob = blockIdx.y >> 1;
        float* C = (ob == 0) ? C0 : (ob == 1) ? C1 : (ob == 2) ? C2 : C3;
        const int n0l = (blockIdx.y & 1) * BN;
#pragma unroll
        for (int nt = 0; nt < 4; nt++) {
            int lc = wn + nt * 8 + tig * 2;
            float2 b2 = *(const float2*)(bias + nglob0 + lc);
            int gc = n0l + lc;
#pragma unroll
            for (int mt = 0; mt < 2; mt++) {
                int gm = m0 + wm + mt * 16 + gr;
                if (gm < M) {
                    float2 v0 = make_float2(acc[mt][nt][0] + b2.x, acc[mt][nt][1] + b2.y);
                    *(float2*)(C + (size_t)gm * NOUT + gc) = v0;
                }
                if (gm + 8 < M) {
                    float2 v1 = make_float2(acc[mt][nt][2] + b2.x, acc[mt][nt][3] + b2.y);
                    *(float2*)(C + (size_t)(gm + 8) * NOUT + gc) = v1;
                }
            }
        }
    } else {
#pragma unroll
        for (int nt = 0; nt < 4; nt++) {
            int gc = nglob0 + wn + nt * 8 + tig * 2;
#pragma unroll
            for (int mt = 0; mt < 2; mt++) {
                int gm = m0 + wm + mt * 16 + gr;
                if (gm < M) {
                    __half2 h0 = __floats2half2_rn(acc[mt][nt][0], acc[mt][nt][1]);
                    *(__half2*)(EH + (size_t)gm * NOUT + gc) = h0;
                }
                if (gm + 8 < M) {
                    __half2 h1 = __floats2half2_rn(acc[mt][nt][2], acc[mt][nt][3]);
                    *(__half2*)(EH + (size_t)(gm + 8) * NOUT + gc) = h1;
                }
            }
        }
    }
}

// ==================== conversion kernels ====================
__global__ void split_feat(const float* __restrict__ X,
                           __nv_bfloat16* __restrict__ hi, __nv_bfloat16* __restrict__ lo,
                           int M, int Kin)
{
    int idx = blockIdx.x * blockDim.x + threadIdx.x;
    if (idx >= M * KPAD) return;
    int k = idx & (KPAD - 1);
    float v = 0.f;
    if (k < Kin) v = X[(size_t)(idx >> 8) * Kin + k];
    __nv_bfloat16 h = __float2bfloat16(v);
    hi[idx] = h;
    lo[idx] = __float2bfloat16(v - __bfloat162float(h));
}

// edge features, original order (streaming); only k < KEDGE written
__global__ void split_feat_edge(const float* __restrict__ ea,
                                __nv_bfloat16* __restrict__ hi, __nv_bfloat16* __restrict__ lo)
{
    int idx = blockIdx.x * blockDim.x + threadIdx.x;
    if (idx >= EE * KPAD) return;
    int k = idx & (KPAD - 1);
    if (k >= KEDGE) return;
    int i = idx >> 8;
    float v = (k < EDD) ? ea[(size_t)i * EDD + k] : 0.f;
    __nv_bfloat16 h = __float2bfloat16(v);
    hi[idx] = h;
    lo[idx] = __float2bfloat16(v - __bfloat162float(h));
}

__global__ void split_weight(const float* __restrict__ W,
                             __nv_bfloat16* __restrict__ hi, __nv_bfloat16* __restrict__ lo,
                             int Kin)
{
    int idx = blockIdx.x * blockDim.x + threadIdx.x;
    if (idx >= NOUT * KPAD) return;
    int n = idx & 255, k = idx >> 8;
    float v = (k < Kin) ? W[(size_t)k * NOUT + n] : 0.f;
    __nv_bfloat16 h = __float2bfloat16(v);
    hi[(size_t)n * KPAD + k] = h;
    lo[(size_t)n * KPAD + k] = __float2bfloat16(v - __bfloat162float(h));
}

__global__ void pack_bias(const float* __restrict__ bq, const float* __restrict__ bk,
                          const float* __restrict__ bv, const float* __restrict__ bs,
                          float* __restrict__ out)
{
    int i = blockIdx.x * blockDim.x + threadIdx.x;
    if (i >= 4 * NOUT) return;
    const float* src = (i < 256) ? bq : (i < 512) ? bk : (i < 768) ? bv : bs;
    out[i] = src[i & 255];
}

// ==================== edge sort-by-dst (once per call) ====================
__global__ void zero_cnt(int* __restrict__ cnt) {
    int i = blockIdx.x * blockDim.x + threadIdx.x;
    if (i < NN) cnt[i] = 0;
}
__global__ void hist_dst(const int* __restrict__ dst, int* __restrict__ cnt) {
    int i = blockIdx.x * blockDim.x + threadIdx.x;
    if (i < EE) atomicAdd(&cnt[dst[i]], 1);
}
__global__ __launch_bounds__(1024) void scan_cnt(const int* __restrict__ cnt,
                                                 int* __restrict__ off, int* __restrict__ pos)
{
    __shared__ int ssum[1024];
    const int tid = threadIdx.x;
    const int PER = (NN + 1023) / 1024;
    const int base = tid * PER;
    int s = 0;
    for (int j = 0; j < PER; j++) {
        int i = base + j;
        if (i < NN) s += cnt[i];
    }
    ssum[tid] = s;
    __syncthreads();
    for (int d = 1; d < 1024; d <<= 1) {
        int t = (tid >= d) ? ssum[tid - d] : 0;
        __syncthreads();
        ssum[tid] += t;
        __syncthreads();
    }
    int run = (tid > 0) ? ssum[tid - 1] : 0;
    for (int j = 0; j < PER; j++) {
        int i = base + j;
        if (i < NN) {
            off[i] = run;
            pos[i] = run;
            run += cnt[i];
        }
    }
    if (tid == 1023) off[NN] = run;
}
__global__ void scatter_edges(const int* __restrict__ dst, const int* __restrict__ src,
                              int* __restrict__ pos, int* __restrict__ order,
                              int* __restrict__ srcs)
{
    int i = blockIdx.x * blockDim.x + threadIdx.x;
    if (i >= EE) return;
    int p = atomicAdd(&pos[dst[i]], 1);
    order[p] = i;
    srcs[p] = src[i];
}

// ==================== fused per-dst attention (softmax + agg + skip + out) ====================
__global__ __launch_bounds__(256) void edge_dst(
    const float* __restrict__ q, const float* __restrict__ k,
    const __half* __restrict__ eemb, const float* __restrict__ v,
    const int* __restrict__ srcs, const int* __restrict__ order,
    const int* __restrict__ off, const float* __restrict__ skip,
    float* __restrict__ outf,
    __nv_bfloat16* __restrict__ hi, __nv_bfloat16* __restrict__ lo,
    int mode)
{
    int w = (blockIdx.x * blockDim.x + threadIdx.x) >> 5;
    if (w >= NN) return;
    const int lane = threadIdx.x & 31;
    const int h = lane >> 3;
    const int part = lane & 7;
    const int co = h * CC + part * 8;

    const int start = off[w], end = off[w + 1];

    const float4* qp = (const float4*)(q + (size_t)w * DNODE + co);
    float4 q0 = qp[0], q1 = qp[1];

    float acc[8] = {0.f, 0.f, 0.f, 0.f, 0.f, 0.f, 0.f, 0.f};
    float den = 0.f;

    for (int i = start; i < end; i++) {
        int s = srcs[i];
        int e = order[i];
        const float4* kp = (const float4*)(k + (size_t)s * DNODE + co);
        float4 k0 = kp[0], k1 = kp[1];

        uint4 eu = *(const uint4*)(eemb + (size_t)e * DNODE + co);
        const __half2* hp = (const __half2*)&eu;
        float2 ea = __half22float2(hp[0]);
        float2 eb = __half22float2(hp[1]);
        float2 ec = __half22float2(hp[2]);
        float2 ed = __half22float2(hp[3]);
        float4 e0 = make_float4(ea.x, ea.y, eb.x, eb.y);
        float4 e1 = make_float4(ec.x, ec.y, ed.x, ed.y);

        float dot = q0.x * (k0.x + e0.x) + q0.y * (k0.y + e0.y)
                  + q0.z * (k0.z + e0.z) + q0.w * (k0.w + e0.w)
                  + q1.x * (k1.x + e1.x) + q1.y * (k1.y + e1.y)
                  + q1.z * (k1.z + e1.z) + q1.w * (k1.w + e1.w);
        dot += __shfl_xor_sync(0xffffffffu, dot, 1);
        dot += __shfl_xor_sync(0xffffffffu, dot, 2);
        dot += __shfl_xor_sync(0xffffffffu, dot, 4);

        float ex = __expf(dot * 0.125f);   // 1/sqrt(64); range-safe in fp32
        den += ex;

        const float4* vp = (const float4*)(v + (size_t)s * DNODE + co);
        float4 v0 = vp[0], v1 = vp[1];
        acc[0] += ex * (v0.x + e0.x); acc[1] += ex * (v0.y + e0.y);
        acc[2] += ex * (v0.z + e0.z); acc[3] += ex * (v0.w + e0.w);
        acc[4] += ex * (v1.x + e1.x); acc[5] += ex * (v1.y + e1.y);
        acc[6] += ex * (v1.z + e1.z); acc[7] += ex * (v1.w + e1.w);
    }

    float inv = 1.0f / (den + 1e-16f);
    const float4* sp = (const float4*)(skip + (size_t)w * DNODE + co);
    float4 s0 = sp[0], s1 = sp[1];
    float r[8];
    r[0] = acc[0] * inv + s0.x; r[1] = acc[1] * inv + s0.y;
    r[2] = acc[2] * inv + s0.z; r[3] = acc[3] * inv + s0.w;
    r[4] = acc[4] * inv + s1.x; r[5] = acc[5] * inv + s1.y;
    r[6] = acc[6] * inv + s1.z; r[7] = acc[7] * inv + s1.w;

    if (mode == 1) {
        ushort4 hv[2], lv[2];
#pragma unroll
        for (int g = 0; g < 2; g++) {
#pragma unroll
            for (int j = 0; j < 4; j++) {
                float x = fmaxf(r[g * 4 + j], 0.f);
                __nv_bfloat16 hb = __float2bfloat16(x);
                __nv_bfloat16 lb = __float2bfloat16(x - __bfloat162float(hb));
                ((unsigned short*)&hv[g])[j] = *(unsigned short*)&hb;
                ((unsigned short*)&lv[g])[j] = *(unsigned short*)&lb;
            }
        }
        size_t base = (size_t)w * KPAD + co;
        *(ushort4*)(hi + base)     = hv[0];
        *(ushort4*)(lo + base)     = lv[0];
        *(ushort4*)(hi + base + 4) = hv[1];
        *(ushort4*)(lo + base + 4) = lv[1];
    } else {
        float4* op = (float4*)(outf + (size_t)w * DNODE + co);
        op[0] = make_float4(r[0], r[1], r[2], r[3]);
        op[1] = make_float4(r[4], r[5], r[6], r[7]);
    }
}

// ==================== host side ====================
static void run_layer(const __nv_bfloat16* ahi, const __nv_bfloat16* alo,
                      const __nv_bfloat16* ehi, const __nv_bfloat16* elo,
                      const __nv_bfloat16* whi, const __nv_bfloat16* wlo, size_t wstride,
                      const float* bias_packed,
                      const int* srcs, const int* order, const int* off,
                      float* q, float* k, float* v, __half* eh, float* skip,
                      float* outf, __nv_bfloat16* out_hi, __nv_bfloat16* out_lo, int mode)
{
    dim3 gn((NN + BM - 1) / BM, 8);
    dim3 ge((EE + BM - 1) / BM, 2);
    gemm_split<<<gn, NTHR, GEMM_SMEM>>>(ahi, alo, whi, wlo, bias_packed,
                                        q, k, v, skip, nullptr, NN, KPAD);
    gemm_split<<<ge, NTHR, GEMM_SMEM>>>(ehi, elo, whi + 4 * wstride, wlo + 4 * wstride,
                                        nullptr, nullptr, nullptr, nullptr, nullptr,
                                        eh, EE, KEDGE);

    edge_dst<<<(NN * 32 + 255) / 256, 256>>>(q, k, eh, v, srcs, order, off, skip,
                                             outf, out_hi, out_lo, mode);
}

extern "C" void kernel_launch(void* const* d_in, const int* in_sizes, int n_in,
                              void* d_out, int out_size)
{
    const float* x   = (const float*)d_in[0];
    const int*   ei  = (const int*)  d_in[1];
    const float* ea  = (const float*)d_in[2];
    // per layer, weight buffer order: Wq, Wk, Wv, Ws, We
    const float* W1[5] = { (const float*)d_in[3],  (const float*)d_in[5],
                           (const float*)d_in[7],  (const float*)d_in[10],
                           (const float*)d_in[9] };
    const float* W2[5] = { (const float*)d_in[12], (const float*)d_in[14],
                           (const float*)d_in[16], (const float*)d_in[19],
                           (const float*)d_in[18] };
    const int Kin[5] = { DNODE, DNODE, DNODE, DNODE, EDD };

    const int* src = ei;
    const int* dst = ei + EE;
    float* out = (float*)d_out;

    float *q, *k, *v, *skip, *bias;
    __half* eh;
    int *cnt, *off, *pos, *order, *srcs;
    __nv_bfloat16 *ahi, *alo, *ehi, *elo, *whi, *wlo;
    cudaGetSymbolAddress((void**)&q,     g_q);
    cudaGetSymbolAddress((void**)&k,     g_k);
    cudaGetSymbolAddress((void**)&v,     g_v);
    cudaGetSymbolAddress((void**)&skip,  g_skip);
    cudaGetSymbolAddress((void**)&eh,    g_eh);
    cudaGetSymbolAddress((void**)&cnt,   g_cnt);
    cudaGetSymbolAddress((void**)&off,   g_off);
    cudaGetSymbolAddress((void**)&pos,   g_pos);
    cudaGetSymbolAddress((void**)&order, g_order);
    cudaGetSymbolAddress((void**)&srcs,  g_srcs);
    cudaGetSymbolAddress((void**)&ahi,   g_ahi);
    cudaGetSymbolAddress((void**)&alo,   g_alo);
    cudaGetSymbolAddress((void**)&ehi,   g_ehi);
    cudaGetSymbolAddress((void**)&elo,   g_elo);
    cudaGetSymbolAddress((void**)&whi,   g_whi);
    cudaGetSymbolAddress((void**)&wlo,   g_wlo);
    cudaGetSymbolAddress((void**)&bias,  g_bias);
    const size_t WS = (size_t)NOUT * KPAD;

    cudaFuncSetAttribute(gemm_split, cudaFuncAttributeMaxDynamicSharedMemorySize, GEMM_SMEM);

    // ---- edge sort by dst (once; shared by both layers) ----
    zero_cnt<<<(NN + 255) / 256, 256>>>(cnt);
    hist_dst<<<(EE + 255) / 256, 256>>>(dst, cnt);
    scan_cnt<<<1, 1024>>>(cnt, off, pos);
    scatter_edges<<<(EE + 255) / 256, 256>>>(dst, src, pos, order, srcs);

    // ---- conversions ----
    for (int i = 0; i < 5; i++) {
        split_weight<<<(NOUT * KPAD + 255) / 256, 256>>>(W1[i], whi + i * WS,       wlo + i * WS,       Kin[i]);
        split_weight<<<(NOUT * KPAD + 255) / 256, 256>>>(W2[i], whi + (5 + i) * WS, wlo + (5 + i) * WS, Kin[i]);
    }
    pack_bias<<<4, 256>>>((const float*)d_in[4],  (const float*)d_in[6],
                          (const float*)d_in[8],  (const float*)d_in[11], bias);
    pack_bias<<<4, 256>>>((const float*)d_in[13], (const float*)d_in[15],
                          (const float*)d_in[17], (const float*)d_in[20], bias + 4 * NOUT);

    split_feat_edge<<<((size_t)EE * KPAD + 255) / 256, 256>>>(ea, ehi, elo);
    split_feat<<<((size_t)NN * KPAD + 255) / 256, 256>>>(x, ahi, alo, NN, DNODE);

    // ---- layer 1: edge_dst writes relu+bf16-split of output (layer-2 input) ----
    run_layer(ahi, alo, ehi, elo, whi, wlo, WS, bias, srcs, order, off,
              q, k, v, eh, skip, nullptr, ahi, alo, 1);

    // ---- layer 2: edge_dst writes d_out ----
    run_layer(ahi, alo, ehi, elo, whi + 5 * WS, wlo + 5 * WS, WS, bias + 4 * NOUT,
              srcs, order, off, q, k, v, eh, skip, out, nullptr, nullptr, 0);
}

// round 15
// speedup vs baseline: 1.9517x; 1.0967x over previous
#include <cuda_runtime.h>
#include <cuda_bf16.h>
#include <cuda_fp16.h>
#include <cstdint>

#define NN 50000
#define EE 250000
#define HH 4
#define CC 64
#define DNODE 256
#define EDD 194
#define KPAD 256
#define NOUT 256
#define KEDGE 224

// ---------------- scratch (device globals; no runtime allocation) ----------------
__device__ float  g_q   [(size_t)NN * DNODE];
__device__ float  g_k   [(size_t)NN * DNODE];
__device__ float  g_v   [(size_t)NN * DNODE];
__device__ float  g_skip[(size_t)NN * DNODE];
__device__ __half g_eh  [(size_t)EE * DNODE];   // edge embeddings, fp16, original order

// edge sort-by-dst (once per call)
__device__ int g_cnt [NN];
__device__ int g_off [NN + 1];
__device__ int g_pos [NN];
__device__ int g_order[EE];
__device__ int g_srcs [EE];

// operand buffers. Node path: bf16 hi/lo. Edge path: g_ehi holds fp16 single-limb
// edge features (g_elo unused for A); weight slots 4 & 9 hold fp16 hi/lo of We.
__device__ __nv_bfloat16 g_ahi[(size_t)NN * KPAD];
__device__ __nv_bfloat16 g_alo[(size_t)NN * KPAD];
__device__ __nv_bfloat16 g_ehi[(size_t)EE * KPAD];
__device__ __nv_bfloat16 g_elo[(size_t)EE * KPAD];
__device__ __nv_bfloat16 g_whi[10][(size_t)NOUT * KPAD];
__device__ __nv_bfloat16 g_wlo[10][(size_t)NOUT * KPAD];
__device__ float g_bias[2][4 * NOUT];

// ==================== split HMMA GEMM (single-barrier pipeline, R14 core) ====================
// MODE 0: bf16, 3 products (Ahi,Alo) x (Bhi,Blo minus lo*lo)   [node GEMMs]
// MODE 1: fp16, 2 products A x (Bhi,Blo), single A limb        [edge GEMM]
#define BM 128
#define BN 128
#define BK 32
#define NTHR 512
#define NSTAGE 3
#define LDS_A 40
#define TSZ (BM * LDS_A)
#define STAGE_ELEMS (4 * TSZ)
#define GEMM_SMEM (NSTAGE * STAGE_ELEMS * 2)

__device__ __forceinline__ uint32_t smem_u32(const void* p) {
    uint32_t a;
    asm("{ .reg .u64 t; cvta.to.shared.u64 t, %1; cvt.u32.u64 %0, t; }" : "=r"(a) : "l"(p));
    return a;
}
__device__ __forceinline__ void cpa16(uint32_t dst, const void* src, int szbytes) {
    asm volatile("cp.async.ca.shared.global [%0], [%1], 16, %2;"
                 :: "r"(dst), "l"(src), "r"(szbytes));
}
#define CP_COMMIT() asm volatile("cp.async.commit_group;" ::: "memory")
#define CP_WAIT(n)  asm volatile("cp.async.wait_group %0;" :: "n"(n) : "memory")

__device__ __forceinline__ void ldsm4(uint32_t* r, uint32_t a) {
    asm volatile("ldmatrix.sync.aligned.m8n8.x4.shared.b16 {%0,%1,%2,%3}, [%4];"
                 : "=r"(r[0]), "=r"(r[1]), "=r"(r[2]), "=r"(r[3]) : "r"(a));
}
__device__ __forceinline__ void mma_bf16(float* c, const uint32_t* a, const uint32_t* b) {
    asm volatile(
        "mma.sync.aligned.m16n8k16.row.col.f32.bf16.bf16.f32 "
        "{%0,%1,%2,%3}, {%4,%5,%6,%7}, {%8,%9}, {%0,%1,%2,%3};"
        : "+f"(c[0]), "+f"(c[1]), "+f"(c[2]), "+f"(c[3])
        : "r"(a[0]), "r"(a[1]), "r"(a[2]), "r"(a[3]), "r"(b[0]), "r"(b[1]));
}
__device__ __forceinline__ void mma_fp16(float* c, const uint32_t* a, const uint32_t* b) {
    asm volatile(
        "mma.sync.aligned.m16n8k16.row.col.f32.f16.f16.f32 "
        "{%0,%1,%2,%3}, {%4,%5,%6,%7}, {%8,%9}, {%0,%1,%2,%3};"
        : "+f"(c[0]), "+f"(c[1]), "+f"(c[2]), "+f"(c[3])
        : "r"(a[0]), "r"(a[1]), "r"(a[2]), "r"(a[3]), "r"(b[0]), "r"(b[1]));
}

// If EH != nullptr: fp16 epilogue into EH (edge GEMM). Else fp32 into C0..C3 + bias.
template <int MODE>
__global__ __launch_bounds__(NTHR) void gemm_split(
    const __nv_bfloat16* __restrict__ Ahi, const __nv_bfloat16* __restrict__ Alo,
    const __nv_bfloat16* __restrict__ Bhi, const __nv_bfloat16* __restrict__ Blo,
    const float* __restrict__ bias,
    float* __restrict__ C0, float* __restrict__ C1,
    float* __restrict__ C2, float* __restrict__ C3,
    __half* __restrict__ EH,
    int M, int K)
{
    extern __shared__ __nv_bfloat16 smem[];

    const int tid  = threadIdx.x;
    const int wid  = tid >> 5;
    const int lane = tid & 31;
    const int m0   = blockIdx.x * BM;
    const int nglob0 = blockIdx.y * BN;

    const int wm = (wid & 3) * 32;
    const int wn = (wid >> 2) * 32;
    const int gr  = lane >> 2;
    const int tig = lane & 3;

    const int r0  = tid >> 2;
    const int cg0 = (tid & 3) * 8;
    const int gmA = m0 + r0;
    const int aok = (gmA < M) ? 16 : 0;
    const size_t arow = (size_t)(aok ? gmA : 0) * KPAD;
    const size_t brow = (size_t)(nglob0 + r0) * KPAD;

    const int nk = K / BK;

    float acc[2][4][4];
#pragma unroll
    for (int i = 0; i < 2; i++)
#pragma unroll
        for (int j = 0; j < 4; j++)
#pragma unroll
            for (int r = 0; r < 4; r++) acc[i][j][r] = 0.f;

    uint32_t sbase = smem_u32(smem);

    auto load_stage = [&](int st, int kc) {
        uint32_t b = sbase + (uint32_t)(st * STAGE_ELEMS) * 2;
        uint32_t d = b + (uint32_t)(r0 * LDS_A + cg0) * 2;
        cpa16(d, Ahi + arow + kc + cg0, aok);
        if (MODE == 0) cpa16(d + (uint32_t)TSZ*2, Alo + arow + kc + cg0, aok);
        cpa16(d + (uint32_t)TSZ*4, Bhi + brow + kc + cg0, 16);
        cpa16(d + (uint32_t)TSZ*6, Blo + brow + kc + cg0, 16);
        CP_COMMIT();
    };

    const int aRow = lane & 15;
    const int aCol = (lane >> 4) * 8;
    const uint32_t aOff = (uint32_t)((wm + aRow) * LDS_A + aCol) * 2;
    const int bRow = wn + (lane & 7) + ((lane >> 4) << 3);
    const int bCol = ((lane >> 3) & 1) * 8;
    const uint32_t bOff = (uint32_t)(bRow * LDS_A + bCol) * 2;

    load_stage(0, 0);
    if (nk > 1) load_stage(1, BK);

    for (int ki = 0; ki < nk; ki++) {
        if (ki + 1 < nk) {
            CP_WAIT(1);
        } else {
            CP_WAIT(0);
        }
        __syncthreads();

        uint32_t stb = sbase + (uint32_t)((ki % NSTAGE) * STAGE_ELEMS) * 2;
        uint32_t aHiB = stb, aLoB = stb + TSZ * 2;
        uint32_t bHiB = stb + TSZ * 4, bLoB = stb + TSZ * 6;

#pragma unroll
        for (int ks = 0; ks < BK; ks += 16) {
            uint32_t ah[2][4], al[2][4];
#pragma unroll
            for (int mt = 0; mt < 2; mt++) {
                uint32_t o = aOff + (uint32_t)(mt * 16 * LDS_A + ks) * 2;
                ldsm4(ah[mt], aHiB + o);
                if (MODE == 0) ldsm4(al[mt], aLoB + o);
            }
            uint32_t bhf[8], blf[8];
#pragma unroll
            for (int p = 0; p < 2; p++) {
                uint32_t o = bOff + (uint32_t)(p * 16 * LDS_A + ks) * 2;
                ldsm4(bhf + 4 * p, bHiB + o);
                ldsm4(blf + 4 * p, bLoB + o);
            }
#pragma unroll
            for (int mt = 0; mt < 2; mt++)
#pragma unroll
                for (int nt = 0; nt < 4; nt++) {
                    if (MODE == 0) {
                        mma_bf16(acc[mt][nt], ah[mt], bhf + nt * 2);
                        mma_bf16(acc[mt][nt], ah[mt], blf + nt * 2);
                        mma_bf16(acc[mt][nt], al[mt], bhf + nt * 2);
                    } else {
                        mma_fp16(acc[mt][nt], ah[mt], bhf + nt * 2);
                        mma_fp16(acc[mt][nt], ah[mt], blf + nt * 2);
                    }
                }
        }

        if (ki + 2 < nk) load_stage((ki + 2) % NSTAGE, (ki + 2) * BK);
    }

    // ---- epilogue ----
    if (EH == nullptr) {
        const int ob = blockIdx.y >> 1;
        float* C = (ob == 0) ? C0 : (ob == 1) ? C1 : (ob == 2) ? C2 : C3;
        const int n0l = (blockIdx.y & 1) * BN;
#pragma unroll
        for (int nt = 0; nt < 4; nt++) {
            int lc = wn + nt * 8 + tig * 2;
            float2 b2 = *(const float2*)(bias + nglob0 + lc);
            int gc = n0l + lc;
#pragma unroll
            for (int mt = 0; mt < 2; mt++) {
                int gm = m0 + wm + mt * 16 + gr;
                if (gm < M) {
                    float2 v0 = make_float2(acc[mt][nt][0] + b2.x, acc[mt][nt][1] + b2.y);
                    *(float2*)(C + (size_t)gm * NOUT + gc) = v0;
                }
                if (gm + 8 < M) {
                    float2 v1 = make_float2(acc[mt][nt][2] + b2.x, acc[mt][nt][3] + b2.y);
                    *(float2*)(C + (size_t)(gm + 8) * NOUT + gc) = v1;
                }
            }
        }
    } else {
#pragma unroll
        for (int nt = 0; nt < 4; nt++) {
            int gc = nglob0 + wn + nt * 8 + tig * 2;
#pragma unroll
            for (int mt = 0; mt < 2; mt++) {
                int gm = m0 + wm + mt * 16 + gr;
                if (gm < M) {
                    __half2 h0 = __floats2half2_rn(acc[mt][nt][0], acc[mt][nt][1]);
                    *(__half2*)(EH + (size_t)gm * NOUT + gc) = h0;
                }
                if (gm + 8 < M) {
                    __half2 h1 = __floats2half2_rn(acc[mt][nt][2], acc[mt][nt][3]);
                    *(__half2*)(EH + (size_t)(gm + 8) * NOUT + gc) = h1;
                }
            }
        }
    }
}

// ==================== conversion kernels ====================
__global__ void split_feat(const float* __restrict__ X,
                           __nv_bfloat16* __restrict__ hi, __nv_bfloat16* __restrict__ lo,
                           int M, int Kin)
{
    int idx = blockIdx.x * blockDim.x + threadIdx.x;
    if (idx >= M * KPAD) return;
    int k = idx & (KPAD - 1);
    float v = 0.f;
    if (k < Kin) v = X[(size_t)(idx >> 8) * Kin + k];
    __nv_bfloat16 h = __float2bfloat16(v);
    hi[idx] = h;
    lo[idx] = __float2bfloat16(v - __bfloat162float(h));
}

// edge features -> single fp16 limb (original order, streaming); only k < KEDGE written
__global__ void feat_edge_f16(const float* __restrict__ ea, __half* __restrict__ hi)
{
    int idx = blockIdx.x * blockDim.x + threadIdx.x;
    if (idx >= EE * KPAD) return;
    int k = idx & (KPAD - 1);
    if (k >= KEDGE) return;
    int i = idx >> 8;
    float v = (k < EDD) ? ea[(size_t)i * EDD + k] : 0.f;
    hi[idx] = __float2half(v);
}

__global__ void split_weight(const float* __restrict__ W,
                             __nv_bfloat16* __restrict__ hi, __nv_bfloat16* __restrict__ lo,
                             int Kin)
{
    int idx = blockIdx.x * blockDim.x + threadIdx.x;
    if (idx >= NOUT * KPAD) return;
    int n = idx & 255, k = idx >> 8;
    float v = (k < Kin) ? W[(size_t)k * NOUT + n] : 0.f;
    __nv_bfloat16 h = __float2bfloat16(v);
    hi[(size_t)n * KPAD + k] = h;
    lo[(size_t)n * KPAD + k] = __float2bfloat16(v - __bfloat162float(h));
}

// weight -> fp16 hi/lo limbs (for the edge GEMM)
__global__ void split_weight_f16(const float* __restrict__ W,
                                 __half* __restrict__ hi, __half* __restrict__ lo,
                                 int Kin)
{
    int idx = blockIdx.x * blockDim.x + threadIdx.x;
    if (idx >= NOUT * KPAD) return;
    int n = idx & 255, k = idx >> 8;
    float v = (k < Kin) ? W[(size_t)k * NOUT + n] : 0.f;
    __half h = __float2half(v);
    hi[(size_t)n * KPAD + k] = h;
    lo[(size_t)n * KPAD + k] = __float2half(v - __half2float(h));
}

__global__ void pack_bias(const float* __restrict__ bq, const float* __restrict__ bk,
                          const float* __restrict__ bv, const float* __restrict__ bs,
                          float* __restrict__ out)
{
    int i = blockIdx.x * blockDim.x + threadIdx.x;
    if (i >= 4 * NOUT) return;
    const float* src = (i < 256) ? bq : (i < 512) ? bk : (i < 768) ? bv : bs;
    out[i] = src[i & 255];
}

// ==================== edge sort-by-dst (once per call) ====================
__global__ void zero_cnt(int* __restrict__ cnt) {
    int i = blockIdx.x * blockDim.x + threadIdx.x;
    if (i < NN) cnt[i] = 0;
}
__global__ void hist_dst(const int* __restrict__ dst, int* __restrict__ cnt) {
    int i = blockIdx.x * blockDim.x + threadIdx.x;
    if (i < EE) atomicAdd(&cnt[dst[i]], 1);
}
__global__ __launch_bounds__(1024) void scan_cnt(const int* __restrict__ cnt,
                                                 int* __restrict__ off, int* __restrict__ pos)
{
    __shared__ int ssum[1024];
    const int tid = threadIdx.x;
    const int PER = (NN + 1023) / 1024;
    const int base = tid * PER;
    int s = 0;
    for (int j = 0; j < PER; j++) {
        int i = base + j;
        if (i < NN) s += cnt[i];
    }
    ssum[tid] = s;
    __syncthreads();
    for (int d = 1; d < 1024; d <<= 1) {
        int t = (tid >= d) ? ssum[tid - d] : 0;
        __syncthreads();
        ssum[tid] += t;
        __syncthreads();
    }
    int run = (tid > 0) ? ssum[tid - 1] : 0;
    for (int j = 0; j < PER; j++) {
        int i = base + j;
        if (i < NN) {
            off[i] = run;
            pos[i] = run;
            run += cnt[i];
        }
    }
    if (tid == 1023) off[NN] = run;
}
__global__ void scatter_edges(const int* __restrict__ dst, const int* __restrict__ src,
                              int* __restrict__ pos, int* __restrict__ order,
                              int* __restrict__ srcs)
{
    int i = blockIdx.x * blockDim.x + threadIdx.x;
    if (i >= EE) return;
    int p = atomicAdd(&pos[dst[i]], 1);
    order[p] = i;
    srcs[p] = src[i];
}

// ==================== fused per-dst attention (softmax + agg + skip + out) ====================
__global__ __launch_bounds__(256) void edge_dst(
    const float* __restrict__ q, const float* __restrict__ k,
    const __half* __restrict__ eemb, const float* __restrict__ v,
    const int* __restrict__ srcs, const int* __restrict__ order,
    const int* __restrict__ off, const float* __restrict__ skip,
    float* __restrict__ outf,
    __nv_bfloat16* __restrict__ hi, __nv_bfloat16* __restrict__ lo,
    int mode)
{
    int w = (blockIdx.x * blockDim.x + threadIdx.x) >> 5;
    if (w >= NN) return;
    const int lane = threadIdx.x & 31;
    const int h = lane >> 3;
    const int part = lane & 7;
    const int co = h * CC + part * 8;

    const int start = off[w], end = off[w + 1];

    const float4* qp = (const float4*)(q + (size_t)w * DNODE + co);
    float4 q0 = qp[0], q1 = qp[1];

    float acc[8] = {0.f, 0.f, 0.f, 0.f, 0.f, 0.f, 0.f, 0.f};
    float den = 0.f;

    for (int i = start; i < end; i++) {
        int s = srcs[i];
        int e = order[i];
        const float4* kp = (const float4*)(k + (size_t)s * DNODE + co);
        float4 k0 = kp[0], k1 = kp[1];

        uint4 eu = *(const uint4*)(eemb + (size_t)e * DNODE + co);
        const __half2* hp = (const __half2*)&eu;
        float2 ea = __half22float2(hp[0]);
        float2 eb = __half22float2(hp[1]);
        float2 ec = __half22float2(hp[2]);
        float2 ed = __half22float2(hp[3]);
        float4 e0 = make_float4(ea.x, ea.y, eb.x, eb.y);
        float4 e1 = make_float4(ec.x, ec.y, ed.x, ed.y);

        float dot = q0.x * (k0.x + e0.x) + q0.y * (k0.y + e0.y)
                  + q0.z * (k0.z + e0.z) + q0.w * (k0.w + e0.w)
                  + q1.x * (k1.x + e1.x) + q1.y * (k1.y + e1.y)
                  + q1.z * (k1.z + e1.z) + q1.w * (k1.w + e1.w);
        dot += __shfl_xor_sync(0xffffffffu, dot, 1);
        dot += __shfl_xor_sync(0xffffffffu, dot, 2);
        dot += __shfl_xor_sync(0xffffffffu, dot, 4);

        float ex = __expf(dot * 0.125f);   // 1/sqrt(64); range-safe in fp32
        den += ex;

        const float4* vp = (const float4*)(v + (size_t)s * DNODE + co);
        float4 v0 = vp[0], v1 = vp[1];
        acc[0] += ex * (v0.x + e0.x); acc[1] += ex * (v0.y + e0.y);
        acc[2] += ex * (v0.z + e0.z); acc[3] += ex * (v0.w + e0.w);
        acc[4] += ex * (v1.x + e1.x); acc[5] += ex * (v1.y + e1.y);
        acc[6] += ex * (v1.z + e1.z); acc[7] += ex * (v1.w + e1.w);
    }

    float inv = 1.0f / (den + 1e-16f);
    const float4* sp = (const float4*)(skip + (size_t)w * DNODE + co);
    float4 s0 = sp[0], s1 = sp[1];
    float r[8];
    r[0] = acc[0] * inv + s0.x; r[1] = acc[1] * inv + s0.y;
    r[2] = acc[2] * inv + s0.z; r[3] = acc[3] * inv + s0.w;
    r[4] = acc[4] * inv + s1.x; r[5] = acc[5] * inv + s1.y;
    r[6] = acc[6] * inv + s1.z; r[7] = acc[7] * inv + s1.w;

    if (mode == 1) {
        ushort4 hv[2], lv[2];
#pragma unroll
        for (int g = 0; g < 2; g++) {
#pragma unroll
            for (int j = 0; j < 4; j++) {
                float x = fmaxf(r[g * 4 + j], 0.f);
                __nv_bfloat16 hb = __float2bfloat16(x);
                __nv_bfloat16 lb = __float2bfloat16(x - __bfloat162float(hb));
                ((unsigned short*)&hv[g])[j] = *(unsigned short*)&hb;
                ((unsigned short*)&lv[g])[j] = *(unsigned short*)&lb;
            }
        }
        size_t base = (size_t)w * KPAD + co;
        *(ushort4*)(hi + base)     = hv[0];
        *(ushort4*)(lo + base)     = lv[0];
        *(ushort4*)(hi + base + 4) = hv[1];
        *(ushort4*)(lo + base + 4) = lv[1];
    } else {
        float4* op = (float4*)(outf + (size_t)w * DNODE + co);
        op[0] = make_float4(r[0], r[1], r[2], r[3]);
        op[1] = make_float4(r[4], r[5], r[6], r[7]);
    }
}

// ==================== host side ====================
static void run_layer(const __nv_bfloat16* ahi, const __nv_bfloat16* alo,
                      const __nv_bfloat16* ehi,
                      const __nv_bfloat16* whi, const __nv_bfloat16* wlo, size_t wstride,
                      const float* bias_packed,
                      const int* srcs, const int* order, const int* off,
                      float* q, float* k, float* v, __half* eh, float* skip,
                      float* outf, __nv_bfloat16* out_hi, __nv_bfloat16* out_lo, int mode)
{
    dim3 gn((NN + BM - 1) / BM, 8);
    dim3 ge((EE + BM - 1) / BM, 2);
    gemm_split<0><<<gn, NTHR, GEMM_SMEM>>>(ahi, alo, whi, wlo, bias_packed,
                                           q, k, v, skip, nullptr, NN, KPAD);
    // edge: single-limb fp16 A, fp16 hi/lo weights (stored in whi/wlo slot 4, reinterpreted)
    gemm_split<1><<<ge, NTHR, GEMM_SMEM>>>(ehi, ehi, whi + 4 * wstride, wlo + 4 * wstride,
                                           nullptr, nullptr, nullptr, nullptr, nullptr,
                                           eh, EE, KEDGE);

    edge_dst<<<(NN * 32 + 255) / 256, 256>>>(q, k, eh, v, srcs, order, off, skip,
                                             outf, out_hi, out_lo, mode);
}

extern "C" void kernel_launch(void* const* d_in, const int* in_sizes, int n_in,
                              void* d_out, int out_size)
{
    const float* x   = (const float*)d_in[0];
    const int*   ei  = (const int*)  d_in[1];
    const float* ea  = (const float*)d_in[2];
    // per layer, weight buffer order: Wq, Wk, Wv, Ws, We
    const float* W1[5] = { (const float*)d_in[3],  (const float*)d_in[5],
                           (const float*)d_in[7],  (const float*)d_in[10],
                           (const float*)d_in[9] };
    const float* W2[5] = { (const float*)d_in[12], (const float*)d_in[14],
                           (const float*)d_in[16], (const float*)d_in[19],
                           (const float*)d_in[18] };
    const int Kin[5] = { DNODE, DNODE, DNODE, DNODE, EDD };

    const int* src = ei;
    const int* dst = ei + EE;
    float* out = (float*)d_out;

    float *q, *k, *v, *skip, *bias;
    __half* eh;
    int *cnt, *off, *pos, *order, *srcs;
    __nv_bfloat16 *ahi, *alo, *ehi, *elo, *whi, *wlo;
    cudaGetSymbolAddress((void**)&q,     g_q);
    cudaGetSymbolAddress((void**)&k,     g_k);
    cudaGetSymbolAddress((void**)&v,     g_v);
    cudaGetSymbolAddress((void**)&skip,  g_skip);
    cudaGetSymbolAddress((void**)&eh,    g_eh);
    cudaGetSymbolAddress((void**)&cnt,   g_cnt);
    cudaGetSymbolAddress((void**)&off,   g_off);
    cudaGetSymbolAddress((void**)&pos,   g_pos);
    cudaGetSymbolAddress((void**)&order, g_order);
    cudaGetSymbolAddress((void**)&srcs,  g_srcs);
    cudaGetSymbolAddress((void**)&ahi,   g_ahi);
    cudaGetSymbolAddress((void**)&alo,   g_alo);
    cudaGetSymbolAddress((void**)&ehi,   g_ehi);
    cudaGetSymbolAddress((void**)&elo,   g_elo);
    cudaGetSymbolAddress((void**)&whi,   g_whi);
    cudaGetSymbolAddress((void**)&wlo,   g_wlo);
    cudaGetSymbolAddress((void**)&bias,  g_bias);
    const size_t WS = (size_t)NOUT * KPAD;

    cudaFuncSetAttribute(gemm_split<0>, cudaFuncAttributeMaxDynamicSharedMemorySize, GEMM_SMEM);
    cudaFuncSetAttribute(gemm_split<1>, cudaFuncAttributeMaxDynamicSharedMemorySize, GEMM_SMEM);

    // ---- edge sort by dst (once; shared by both layers) ----
    zero_cnt<<<(NN + 255) / 256, 256>>>(cnt);
    hist_dst<<<(EE + 255) / 256, 256>>>(dst, cnt);
    scan_cnt<<<1, 1024>>>(cnt, off, pos);
    scatter_edges<<<(EE + 255) / 256, 256>>>(dst, src, pos, order, srcs);

    // ---- conversions ----
    for (int i = 0; i < 4; i++) {   // node weights: bf16 hi/lo
        split_weight<<<(NOUT * KPAD + 255) / 256, 256>>>(W1[i], whi + i * WS,       wlo + i * WS,       Kin[i]);
        split_weight<<<(NOUT * KPAD + 255) / 256, 256>>>(W2[i], whi + (5 + i) * WS, wlo + (5 + i) * WS, Kin[i]);
    }
    // edge weights (slot 4, 9): fp16 hi/lo
    split_weight_f16<<<(NOUT * KPAD + 255) / 256, 256>>>(W1[4], (__half*)(whi + 4 * WS), (__half*)(wlo + 4 * WS), EDD);
    split_weight_f16<<<(NOUT * KPAD + 255) / 256, 256>>>(W2[4], (__half*)(whi + 9 * WS), (__half*)(wlo + 9 * WS), EDD);

    pack_bias<<<4, 256>>>((const float*)d_in[4],  (const float*)d_in[6],
                          (const float*)d_in[8],  (const float*)d_in[11], bias);
    pack_bias<<<4, 256>>>((const float*)d_in[13], (const float*)d_in[15],
                          (const float*)d_in[17], (const float*)d_in[20], bias + 4 * NOUT);

    feat_edge_f16<<<((size_t)EE * KPAD + 255) / 256, 256>>>(ea, (__half*)ehi);
    split_feat<<<((size_t)NN * KPAD + 255) / 256, 256>>>(x, ahi, alo, NN, DNODE);

    // ---- layer 1: edge_dst writes relu+bf16-split of output (layer-2 input) ----
    run_layer(ahi, alo, ehi, whi, wlo, WS, bias, srcs, order, off,
              q, k, v, eh, skip, nullptr, ahi, alo, 1);

    // ---- layer 2: edge_dst writes d_out ----
    run_layer(ahi, alo, ehi, whi + 5 * WS, wlo + 5 * WS, WS, bias + 4 * NOUT,
              srcs, order, off, q, k, v, eh, skip, out, nullptr, nullptr, 0);
}